// round 6
// baseline (speedup 1.0000x reference)
#include <cuda_runtime.h>
#include <cstdint>

// BoundingBox: mask [N,1,H,W] fp32 -> bbox [N,4] float32 (ymin, xmin, ymax, xmax),
// hit = (v >= 0.5f). Reference: lo = first hit, hi = last hit + 1; no hit -> (0, full).
//
// Latency-floor version. One WARP per image handles all four directions:
//   - 4 front-batched probe loads (row 0 / row H-1 cols 0-31, col 0 / col W-1 rows 0-31)
//     issued back-to-back: MLP=4, ONE overlapped DRAM/L2 round trip.
//   - 4 ballots; if all four edges hit (P(miss) ~ 4*2^-32 on uniform data) lane 0
//     writes the whole bbox as a single STG.128 and the warp retires.
//   - Cold exact fallback: full edge-inward batch scans (restart at index 0),
//     preserving the reference's no-hit conventions (lo=0, hi=full).
// Grid: 32 blocks x 128 threads (4 warps = 4 images each) -> fast ramp/drain.

#define BB_H 512
#define BB_W 512
#define BB_THRESH 0.5f
#define FULLMASK 0xFFFFFFFFu

__device__ __forceinline__ int scan_rows_fwd(const float* __restrict__ img, int lane) {
    for (int r = 0; r < BB_H; ++r)
        for (int k = 0; k < BB_W / 32; ++k)
            if (__ballot_sync(FULLMASK, img[(size_t)r * BB_W + k * 32 + lane] >= BB_THRESH))
                return r;
    return 0;                 // no hit -> 0
}
__device__ __forceinline__ int scan_rows_bwd(const float* __restrict__ img, int lane) {
    for (int r = BB_H - 1; r >= 0; --r)
        for (int k = 0; k < BB_W / 32; ++k)
            if (__ballot_sync(FULLMASK, img[(size_t)r * BB_W + k * 32 + lane] >= BB_THRESH))
                return r + 1;
    return BB_H;              // no hit -> full
}
__device__ __forceinline__ int scan_cols_fwd(const float* __restrict__ img, int lane) {
    for (int c = 0; c < BB_W; ++c)
        for (int k = 0; k < BB_H / 32; ++k)
            if (__ballot_sync(FULLMASK, img[(size_t)(k * 32 + lane) * BB_W + c] >= BB_THRESH))
                return c;
    return 0;
}
__device__ __forceinline__ int scan_cols_bwd(const float* __restrict__ img, int lane) {
    for (int c = BB_W - 1; c >= 0; --c)
        for (int k = 0; k < BB_H / 32; ++k)
            if (__ballot_sync(FULLMASK, img[(size_t)(k * 32 + lane) * BB_W + c] >= BB_THRESH))
                return c + 1;
    return BB_W;
}

__global__ __launch_bounds__(128, 8)
void BoundingBox_2834678415682_kernel(const float* __restrict__ mask,
                                      float* __restrict__ out, int N) {
    const int lane = threadIdx.x & 31;
    const int n = blockIdx.x * 4 + (threadIdx.x >> 5);   // one warp per image
    if (n >= N) return;

    const float* __restrict__ img = mask + (size_t)n * BB_H * BB_W;

    // Front-batched edge probes (4 independent loads -> one overlapped trip).
    float pr0 = img[lane];                                  // row 0,    cols 0-31
    float pr1 = img[(size_t)(BB_H - 1) * BB_W + lane];      // row H-1,  cols 0-31
    float pc0 = img[(size_t)lane * BB_W];                   // col 0,    rows 0-31
    float pc1 = img[(size_t)lane * BB_W + (BB_W - 1)];      // col W-1,  rows 0-31

    unsigned b0 = __ballot_sync(FULLMASK, pr0 >= BB_THRESH);
    unsigned b1 = __ballot_sync(FULLMASK, pr1 >= BB_THRESH);
    unsigned b2 = __ballot_sync(FULLMASK, pc0 >= BB_THRESH);
    unsigned b3 = __ballot_sync(FULLMASK, pc1 >= BB_THRESH);

    if (b0 && b1 && b2 && b3) {
        if (lane == 0) {
            float4 res = make_float4(0.0f, 0.0f, (float)BB_H, (float)BB_W);
            *reinterpret_cast<float4*>(out + n * 4) = res;
        }
        return;
    }

    // Cold exact path (warp-uniform branches; ballots keep the warp converged).
    float ymin = b0 ? 0.0f          : (float)scan_rows_fwd(img, lane);
    float ymax = b1 ? (float)BB_H   : (float)scan_rows_bwd(img, lane);
    float xmin = b2 ? 0.0f          : (float)scan_cols_fwd(img, lane);
    float xmax = b3 ? (float)BB_W   : (float)scan_cols_bwd(img, lane);

    if (lane == 0) {
        float4 res = make_float4(ymin, xmin, ymax, xmax);
        *reinterpret_cast<float4*>(out + n * 4) = res;
    }
}

extern "C" void kernel_launch(void* const* d_in, const int* in_sizes, int n_in,
                              void* d_out, int out_size) {
    const float* mask = (const float*)d_in[0];
    float* out = (float*)d_out;

    const int N = in_sizes[0] / (BB_H * BB_W);
    const int nblk = (N + 3) / 4;

    BoundingBox_2834678415682_kernel<<<nblk, 128>>>(mask, out, N);
}